// round 8
// baseline (speedup 1.0000x reference)
#include <cuda_runtime.h>
#include <math.h>
#include <stdint.h>

// GroupBRouter fused router — 3xTF32 mma.sync GEMM core (fp32-accurate).
// logits = tokens(65536x1024) @ W_g^T(1024x64) + b_g ; softmax; floor; cap; top-2.
// B=16, N=4096, D=1024, E=64.  mma.sync.m16n8k8.tf32 is base-sm_103 legal
// (tcgen05 is 'a'-gated in this toolchain and unusable).

namespace {
constexpr int D   = 1024;
constexpr int E   = 64;
constexpr int BM  = 128;   // tokens per CTA
constexpr int BK  = 32;    // K chunk
constexpr int TPB = 128;   // 4 warps; each warp: 32 token rows x 64 experts
constexpr int AST = 36;    // staging row stride (floats); 36 % 32 = 4 -> frag loads conflict-free
constexpr int LST = 65;    // epilogue scratch stride
constexpr int A_ELEMS = BM * AST;                 // 4608 floats per A split tile
constexpr int B_ELEMS = E  * AST;                 // 2304 floats per B split tile
constexpr int OFF_A0 = 0;
constexpr int OFF_A1 = A_ELEMS;
constexpr int OFF_B0 = 2 * A_ELEMS;
constexpr int OFF_B1 = 2 * A_ELEMS + B_ELEMS;
constexpr int SMEM_FLOATS = 2 * A_ELEMS + 2 * B_ELEMS;   // 13824 floats = 55296 B
}

__device__ __forceinline__ uint32_t cvt_tf32(float x) {
    uint32_t u; asm("cvt.rna.tf32.f32 %0, %1;" : "=r"(u) : "f"(x)); return u;
}
// exact-ish 2-way tf32 split: x = hi + lo + O(2^-24 x)
__device__ __forceinline__ void split2(float x, float& hi, float& lo) {
    uint32_t h = cvt_tf32(x);
    hi = __uint_as_float(h);
    lo = __uint_as_float(cvt_tf32(x - hi));
}
__device__ __forceinline__ void mma_tf32(float* d, const uint32_t* a, const uint32_t* b) {
    asm volatile(
        "mma.sync.aligned.m16n8k8.row.col.f32.tf32.tf32.f32 "
        "{%0,%1,%2,%3}, {%4,%5,%6,%7}, {%8,%9}, {%0,%1,%2,%3};"
        : "+f"(d[0]), "+f"(d[1]), "+f"(d[2]), "+f"(d[3])
        : "r"(a[0]), "r"(a[1]), "r"(a[2]), "r"(a[3]), "r"(b[0]), "r"(b[1]));
}

__global__ __launch_bounds__(TPB, 4)
void router_kernel(const float* __restrict__ tokens,
                   const int*   __restrict__ tsteps,
                   const float* __restrict__ Wg,
                   const float* __restrict__ bg,
                   float* __restrict__ out)
{
    extern __shared__ __align__(16) float smem[];
    float* As0 = smem + OFF_A0;   // [BM][AST] tf32-hi of tokens, row-major k
    float* As1 = smem + OFF_A1;   // tf32-lo
    float* Bs0 = smem + OFF_B0;   // [E][AST]  tf32-hi of W
    float* Bs1 = smem + OFF_B1;   // tf32-lo
    float* Ls  = smem;            // [BM][LST] epilogue scratch (reuse)

    const int tid  = threadIdx.x;
    const int w    = tid >> 5;
    const int lane = tid & 31;
    const int r    = lane >> 2;   // 0..7
    const int tg   = lane & 3;    // 0..3
    const int m0   = blockIdx.x * BM;

    // acc[mt][nt][0..3]: m16n8 tile (w*32 + mt*16, nt*8)
    float acc[2][8][4];
    #pragma unroll
    for (int mt = 0; mt < 2; ++mt)
        #pragma unroll
        for (int nt = 0; nt < 8; ++nt)
            #pragma unroll
            for (int i = 0; i < 4; ++i) acc[mt][nt][i] = 0.f;

    for (int k0 = 0; k0 < D; k0 += BK) {
        __syncthreads();   // previous chunk's readers done
        // ---- stage A: thread tid owns token row tid; 8 float4 along k ----
        {
            const float* src = tokens + (size_t)(m0 + tid) * D + k0;
            float* d0 = As0 + tid * AST;
            float* d1 = As1 + tid * AST;
            #pragma unroll
            for (int it = 0; it < 8; ++it) {
                float4 v = *reinterpret_cast<const float4*>(src + it * 4);
                float4 h, l;
                split2(v.x, h.x, l.x); split2(v.y, h.y, l.y);
                split2(v.z, h.z, l.z); split2(v.w, h.w, l.w);
                *reinterpret_cast<float4*>(d0 + it * 4) = h;
                *reinterpret_cast<float4*>(d1 + it * 4) = l;
            }
        }
        // ---- stage B: thread tid -> expert row tid>>1, half-k (tid&1) ----
        {
            int e   = tid >> 1;
            int kq0 = (tid & 1) * 16;
            const float* src = Wg + (size_t)e * D + k0 + kq0;
            float* d0 = Bs0 + e * AST + kq0;
            float* d1 = Bs1 + e * AST + kq0;
            #pragma unroll
            for (int it = 0; it < 4; ++it) {
                float4 v = *reinterpret_cast<const float4*>(src + it * 4);
                float4 h, l;
                split2(v.x, h.x, l.x); split2(v.y, h.y, l.y);
                split2(v.z, h.z, l.z); split2(v.w, h.w, l.w);
                *reinterpret_cast<float4*>(d0 + it * 4) = h;
                *reinterpret_cast<float4*>(d1 + it * 4) = l;
            }
        }
        __syncthreads();

        // ---- 4 ksteps of k8; 3 products per (mt,nt) into same accumulator ----
        #pragma unroll
        for (int ks = 0; ks < 4; ++ks) {
            const int k = ks * 8;
            uint32_t A0[2][4], A1[2][4];
            #pragma unroll
            for (int mt = 0; mt < 2; ++mt) {
                const int rb = w * 32 + mt * 16;
                const float* p0 = As0 + k + tg;
                const float* p1 = As1 + k + tg;
                A0[mt][0] = __float_as_uint(p0[(rb + r)     * AST]);
                A0[mt][1] = __float_as_uint(p0[(rb + r + 8) * AST]);
                A0[mt][2] = __float_as_uint(p0[(rb + r)     * AST + 4]);
                A0[mt][3] = __float_as_uint(p0[(rb + r + 8) * AST + 4]);
                A1[mt][0] = __float_as_uint(p1[(rb + r)     * AST]);
                A1[mt][1] = __float_as_uint(p1[(rb + r + 8) * AST]);
                A1[mt][2] = __float_as_uint(p1[(rb + r)     * AST + 4]);
                A1[mt][3] = __float_as_uint(p1[(rb + r + 8) * AST + 4]);
            }
            #pragma unroll
            for (int nt = 0; nt < 8; ++nt) {
                const int nb = nt * 8 + r;
                uint32_t B0[2], B1[2];
                B0[0] = __float_as_uint(Bs0[nb * AST + k + tg]);
                B0[1] = __float_as_uint(Bs0[nb * AST + k + tg + 4]);
                B1[0] = __float_as_uint(Bs1[nb * AST + k + tg]);
                B1[1] = __float_as_uint(Bs1[nb * AST + k + tg + 4]);
                #pragma unroll
                for (int mt = 0; mt < 2; ++mt) {
                    mma_tf32(acc[mt][nt], A0[mt], B0);  // hi*hi
                    mma_tf32(acc[mt][nt], A0[mt], B1);  // hi*lo
                    mma_tf32(acc[mt][nt], A1[mt], B0);  // lo*hi
                }
            }
        }
    }
    __syncthreads();   // all mma smem reads done before scratch reuse

    // ---- write logits (+bias) to per-token scratch ----
    #pragma unroll
    for (int mt = 0; mt < 2; ++mt) {
        const int rb = w * 32 + mt * 16;
        #pragma unroll
        for (int nt = 0; nt < 8; ++nt) {
            const int c0 = nt * 8 + 2 * tg;
            const float b0 = __ldg(bg + c0);
            const float b1 = __ldg(bg + c0 + 1);
            Ls[(rb + r)     * LST + c0]     = acc[mt][nt][0] + b0;
            Ls[(rb + r)     * LST + c0 + 1] = acc[mt][nt][1] + b1;
            Ls[(rb + r + 8) * LST + c0]     = acc[mt][nt][2] + b0;
            Ls[(rb + r + 8) * LST + c0 + 1] = acc[mt][nt][3] + b1;
        }
    }
    __syncthreads();

    // ---- per-token epilogue: thread tid owns token (m0 + tid) [R1-proven] ----
    {
        float* row = Ls + tid * LST;

        float mx = row[0];
        for (int j = 1; j < E; ++j) mx = fmaxf(mx, row[j]);
        float s = 0.f;
        for (int j = 0; j < E; ++j) {
            float e = expf(row[j] - mx);
            row[j] = e;
            s += e;
        }
        float inv = 1.0f / s;

        int   gtok = m0 + tid;
        float tn   = (float)tsteps[gtok >> 12] / 1000.0f;
        float cap  = 0.5f + 1.1f * tn;

        float Se = 0.f, Sh = 0.f;
        for (int j = 0; j < E; ++j) {
            float q  = 0.85f * (row[j] * inv) + 0.00234375f;   // floor: 0.85p + 0.15/64
            float ex = fmaxf(q - cap, 0.f);
            float cp = q - ex;
            Se += ex;
            Sh += fmaxf(cap - cp, 0.f);
            row[j] = cp;
        }
        float invSh = 1.0f / fmaxf(Sh, 1e-8f);

        float v1 = -INFINITY, v2 = -INFINITY;
        int   i1 = 0, i2 = 0;
        for (int j = 0; j < E; ++j) {
            float cp = row[j];
            float f  = cp + Se * (fmaxf(cap - cp, 0.f) * invSh);
            if (f > v1)      { v2 = v1; i2 = i1; v1 = f; i1 = j; }
            else if (f > v2) { v2 = f;  i2 = j; }
        }

        for (int j = 0; j < E; ++j) row[j] = 0.f;
        row[i1] = v1;
        row[i2] = v2;
    }
    __syncthreads();

    // ---- coalesced store of the 128x64 gate tile ----
    float* ob = out + (size_t)m0 * E;
    for (int i = tid; i < BM * E; i += TPB)
        ob[i] = Ls[(i >> 6) * LST + (i & 63)];
}

extern "C" void kernel_launch(void* const* d_in, const int* in_sizes, int n_in,
                              void* d_out, int out_size)
{
    const float* tokens = nullptr;
    const int*   tarr   = nullptr;
    const float* Wg     = nullptr;
    const float* bg     = nullptr;
    for (int i = 0; i < n_in; ++i) {
        switch (in_sizes[i]) {
            case 16 * 4096 * 1024: tokens = (const float*)d_in[i]; break;
            case 16:               tarr   = (const int*)d_in[i];   break;
            case 64 * 1024:        Wg     = (const float*)d_in[i]; break;
            case 64:               bg     = (const float*)d_in[i]; break;
        }
    }
    static int smem_set = 0;
    if (!smem_set) {
        cudaFuncSetAttribute(router_kernel,
                             cudaFuncAttributeMaxDynamicSharedMemorySize,
                             SMEM_FLOATS * (int)sizeof(float));
        smem_set = 1;
    }
    router_kernel<<<512, TPB, SMEM_FLOATS * sizeof(float)>>>(
        tokens, tarr, Wg, bg, (float*)d_out);
}

// round 11
// speedup vs baseline: 1.3642x; 1.3642x over previous
#include <cuda_runtime.h>
#include <math.h>
#include <stdint.h>

// GroupBRouter fused router — 3xTF32 mma.sync GEMM core, ILP-restructured.
// logits = tokens(65536x1024) @ W_g^T(1024x64) + b_g ; softmax; floor; cap; top-2.
// B=16, N=4096, D=1024, E=64.

namespace {
constexpr int D   = 1024;
constexpr int E   = 64;
constexpr int BM  = 128;   // tokens per CTA
constexpr int BK  = 32;    // K chunk
constexpr int TPB = 256;   // 8 warps; warp tile = 16 tokens x 64 experts
constexpr int AST = 36;    // staging row stride (floats); frag loads conflict-free
constexpr int LST = 65;    // epilogue scratch stride
constexpr int A_ELEMS = BM * AST;      // 4608
constexpr int B_ELEMS = E  * AST;      // 2304
constexpr int OFF_A0 = 0;
constexpr int OFF_A1 = A_ELEMS;
constexpr int OFF_B0 = 2 * A_ELEMS;
constexpr int OFF_B1 = 2 * A_ELEMS + B_ELEMS;
constexpr int SMEM_FLOATS = 2 * A_ELEMS + 2 * B_ELEMS;   // 13824 = 55296 B
}

__device__ __forceinline__ uint32_t cvt_tf32(float x) {
    uint32_t u; asm("cvt.rna.tf32.f32 %0, %1;" : "=r"(u) : "f"(x)); return u;
}
// 2-way tf32 split: x = hi + lo + O(2^-24 x)
__device__ __forceinline__ void split2(float x, float& hi, float& lo) {
    hi = __uint_as_float(cvt_tf32(x));
    lo = __uint_as_float(cvt_tf32(x - hi));
}
__device__ __forceinline__ void mma_tf32(float* d, const uint32_t* a, const uint32_t* b) {
    asm volatile(
        "mma.sync.aligned.m16n8k8.row.col.f32.tf32.tf32.f32 "
        "{%0,%1,%2,%3}, {%4,%5,%6,%7}, {%8,%9}, {%0,%1,%2,%3};"
        : "+f"(d[0]), "+f"(d[1]), "+f"(d[2]), "+f"(d[3])
        : "r"(a[0]), "r"(a[1]), "r"(a[2]), "r"(a[3]), "r"(b[0]), "r"(b[1]));
}

__global__ __launch_bounds__(TPB, 2)
void router_kernel(const float* __restrict__ tokens,
                   const int*   __restrict__ tsteps,
                   const float* __restrict__ Wg,
                   const float* __restrict__ bg,
                   float* __restrict__ out)
{
    extern __shared__ __align__(16) float smem[];
    float* As0 = smem + OFF_A0;   // [BM][AST] tf32-hi of tokens
    float* As1 = smem + OFF_A1;   // tf32-lo
    float* Bs0 = smem + OFF_B0;   // [E][AST]  tf32-hi of W
    float* Bs1 = smem + OFF_B1;   // tf32-lo
    float* Ls  = smem;            // [BM][LST] epilogue scratch (reuse)

    const int tid  = threadIdx.x;
    const int w    = tid >> 5;    // 0..7
    const int lane = tid & 31;
    const int r    = lane >> 2;   // 0..7
    const int tg   = lane & 3;    // 0..3
    const int m0   = blockIdx.x * BM;
    const int rb   = w * 16;      // warp's token-row base

    // acc[nt][0..3]: m16n8 tile (rb, nt*8)
    float acc[8][4];
    #pragma unroll
    for (int nt = 0; nt < 8; ++nt)
        #pragma unroll
        for (int i = 0; i < 4; ++i) acc[nt][i] = 0.f;

    for (int k0 = 0; k0 < D; k0 += BK) {
        __syncthreads();   // previous chunk's fragment readers done
        // ---- stage A: thread -> token row tid>>1, k-half (tid&1)*16 ----
        {
            const int row = tid >> 1;
            const int kh  = (tid & 1) * 16;
            const float* src = tokens + (size_t)(m0 + row) * D + k0 + kh;
            float* d0 = As0 + row * AST + kh;
            float* d1 = As1 + row * AST + kh;
            #pragma unroll
            for (int it = 0; it < 4; ++it) {
                float4 v = *reinterpret_cast<const float4*>(src + it * 4);
                float4 h, l;
                split2(v.x, h.x, l.x); split2(v.y, h.y, l.y);
                split2(v.z, h.z, l.z); split2(v.w, h.w, l.w);
                *reinterpret_cast<float4*>(d0 + it * 4) = h;
                *reinterpret_cast<float4*>(d1 + it * 4) = l;
            }
        }
        // ---- stage B: thread -> expert row tid>>2, k-quarter (tid&3)*8 ----
        {
            const int e  = tid >> 2;
            const int kq = (tid & 3) * 8;
            const float* src = Wg + (size_t)e * D + k0 + kq;
            float* d0 = Bs0 + e * AST + kq;
            float* d1 = Bs1 + e * AST + kq;
            #pragma unroll
            for (int it = 0; it < 2; ++it) {
                float4 v = *reinterpret_cast<const float4*>(src + it * 4);
                float4 h, l;
                split2(v.x, h.x, l.x); split2(v.y, h.y, l.y);
                split2(v.z, h.z, l.z); split2(v.w, h.w, l.w);
                *reinterpret_cast<float4*>(d0 + it * 4) = h;
                *reinterpret_cast<float4*>(d1 + it * 4) = l;
            }
        }
        __syncthreads();

        // ---- 4 k-steps; preload ALL fragments, then 3 sweeps of 8 indep MMAs ----
        #pragma unroll
        for (int ks = 0; ks < 4; ++ks) {
            const int k = ks * 8;
            uint32_t A0[4], A1[4];
            {
                const float* p0 = As0 + k + tg;
                const float* p1 = As1 + k + tg;
                A0[0] = __float_as_uint(p0[(rb + r)     * AST]);
                A0[1] = __float_as_uint(p0[(rb + r + 8) * AST]);
                A0[2] = __float_as_uint(p0[(rb + r)     * AST + 4]);
                A0[3] = __float_as_uint(p0[(rb + r + 8) * AST + 4]);
                A1[0] = __float_as_uint(p1[(rb + r)     * AST]);
                A1[1] = __float_as_uint(p1[(rb + r + 8) * AST]);
                A1[2] = __float_as_uint(p1[(rb + r)     * AST + 4]);
                A1[3] = __float_as_uint(p1[(rb + r + 8) * AST + 4]);
            }
            uint32_t B0[8][2], B1[8][2];
            #pragma unroll
            for (int nt = 0; nt < 8; ++nt) {
                const int nb = nt * 8 + r;
                B0[nt][0] = __float_as_uint(Bs0[nb * AST + k + tg]);
                B0[nt][1] = __float_as_uint(Bs0[nb * AST + k + tg + 4]);
                B1[nt][0] = __float_as_uint(Bs1[nb * AST + k + tg]);
                B1[nt][1] = __float_as_uint(Bs1[nb * AST + k + tg + 4]);
            }
            // pass 0: hi*hi — 8 independent MMAs
            #pragma unroll
            for (int nt = 0; nt < 8; ++nt) mma_tf32(acc[nt], A0, B0[nt]);
            // pass 1: hi*lo
            #pragma unroll
            for (int nt = 0; nt < 8; ++nt) mma_tf32(acc[nt], A0, B1[nt]);
            // pass 2: lo*hi
            #pragma unroll
            for (int nt = 0; nt < 8; ++nt) mma_tf32(acc[nt], A1, B0[nt]);
        }
    }
    __syncthreads();   // all fragment reads done before scratch reuse

    // ---- write logits (+bias) to per-token scratch ----
    #pragma unroll
    for (int nt = 0; nt < 8; ++nt) {
        const int c0 = nt * 8 + 2 * tg;
        const float b0 = __ldg(bg + c0);
        const float b1 = __ldg(bg + c0 + 1);
        Ls[(rb + r)     * LST + c0]     = acc[nt][0] + b0;
        Ls[(rb + r)     * LST + c0 + 1] = acc[nt][1] + b1;
        Ls[(rb + r + 8) * LST + c0]     = acc[nt][2] + b0;
        Ls[(rb + r + 8) * LST + c0 + 1] = acc[nt][3] + b1;
    }
    __syncthreads();

    // ---- per-token epilogue: threads 0..127 own one token each (R1-proven) ----
    if (tid < BM) {
        float* row = Ls + tid * LST;

        float mx = row[0];
        for (int j = 1; j < E; ++j) mx = fmaxf(mx, row[j]);
        float s = 0.f;
        for (int j = 0; j < E; ++j) {
            float e = expf(row[j] - mx);
            row[j] = e;
            s += e;
        }
        float inv = 1.0f / s;

        int   gtok = m0 + tid;
        float tn   = (float)tsteps[gtok >> 12] / 1000.0f;
        float cap  = 0.5f + 1.1f * tn;

        float Se = 0.f, Sh = 0.f;
        for (int j = 0; j < E; ++j) {
            float q  = 0.85f * (row[j] * inv) + 0.00234375f;   // floor: 0.85p + 0.15/64
            float ex = fmaxf(q - cap, 0.f);
            float cp = q - ex;
            Se += ex;
            Sh += fmaxf(cap - cp, 0.f);
            row[j] = cp;
        }
        float invSh = 1.0f / fmaxf(Sh, 1e-8f);

        float v1 = -INFINITY, v2 = -INFINITY;
        int   i1 = 0, i2 = 0;
        for (int j = 0; j < E; ++j) {
            float cp = row[j];
            float f  = cp + Se * (fmaxf(cap - cp, 0.f) * invSh);
            if (f > v1)      { v2 = v1; i2 = i1; v1 = f; i1 = j; }
            else if (f > v2) { v2 = f;  i2 = j; }
        }

        for (int j = 0; j < E; ++j) row[j] = 0.f;
        row[i1] = v1;
        row[i2] = v2;
    }
    __syncthreads();

    // ---- coalesced store of the 128x64 gate tile ----
    float* ob = out + (size_t)m0 * E;
    for (int i = tid; i < BM * E; i += TPB)
        ob[i] = Ls[(i >> 6) * LST + (i & 63)];
}

extern "C" void kernel_launch(void* const* d_in, const int* in_sizes, int n_in,
                              void* d_out, int out_size)
{
    const float* tokens = nullptr;
    const int*   tarr   = nullptr;
    const float* Wg     = nullptr;
    const float* bg     = nullptr;
    for (int i = 0; i < n_in; ++i) {
        switch (in_sizes[i]) {
            case 16 * 4096 * 1024: tokens = (const float*)d_in[i]; break;
            case 16:               tarr   = (const int*)d_in[i];   break;
            case 64 * 1024:        Wg     = (const float*)d_in[i]; break;
            case 64:               bg     = (const float*)d_in[i]; break;
        }
    }
    static int smem_set = 0;
    if (!smem_set) {
        cudaFuncSetAttribute(router_kernel,
                             cudaFuncAttributeMaxDynamicSharedMemorySize,
                             SMEM_FLOATS * (int)sizeof(float));
        smem_set = 1;
    }
    router_kernel<<<512, TPB, SMEM_FLOATS * sizeof(float)>>>(
        tokens, tarr, Wg, bg, (float*)d_out);
}